// round 6
// baseline (speedup 1.0000x reference)
#include <cuda_runtime.h>
#include <cuda_bf16.h>
#include <mma.h>
#include <stdint.h>
#include <math.h>
using namespace nvcuda;

#define NTH 512
#define RTOT 65536L

// Pre-split bf16 hi/lo copies of the fp32 inputs (written by presplit kernels).
__device__ __nv_bfloat16 g_xh[RTOT * 512], g_xl[RTOT * 512];
__device__ __nv_bfloat16 g_ewh[256 * 512], g_ewl[256 * 512];
__device__ __nv_bfloat16 g_dwh[512 * 256], g_dwl[512 * 256];
__device__ __nv_bfloat16 g_mh[64 * 256],  g_ml[64 * 256];

// ---- smem offsets (bytes); regions are phase-unioned ----
#define P_XH(b) ((b) * 20480)
#define P_XL(b) ((b) * 20480 + 10240)
#define P_WH(b) (40960 + (b) * 40960)
#define P_WL(b) (61440 + (b) * 40960)
#define EH_O  0
#define EL_O  67584
#define STG_O 135168
#define MKH_O 169984
#define MKL_O 187392
#define ATH_O 169984
#define ATL_O 188416
#define M3H_O 0
#define M3L_O 33792
#define MH_O  0
#define ML_O  67584
#define B4H(b) (169984 + (b) * 20480)
#define B4L(b) (180224 + (b) * 20480)
#define SMEM_TOTAL 210944

typedef wmma::fragment<wmma::matrix_a, 16,16,16, __nv_bfloat16, wmma::row_major> FragA;
typedef wmma::fragment<wmma::matrix_b, 16,16,16, __nv_bfloat16, wmma::col_major> FragBc;
typedef wmma::fragment<wmma::matrix_b, 16,16,16, __nv_bfloat16, wmma::row_major> FragBr;
typedef wmma::fragment<wmma::accumulator, 16,16,16, float> FragC;

__device__ __forceinline__ uint32_t bfpair(float a, float b) {
    __nv_bfloat162 t = __floats2bfloat162_rn(a, b);
    return *reinterpret_cast<uint32_t*>(&t);
}
__device__ __forceinline__ void split4(const float4 v, uint2 &h, uint2 &l) {
    __nv_bfloat16 hx = __float2bfloat16(v.x), hy = __float2bfloat16(v.y);
    __nv_bfloat16 hz = __float2bfloat16(v.z), hw = __float2bfloat16(v.w);
    h.x = ((uint32_t)__bfloat16_as_ushort(hy) << 16) | (uint32_t)__bfloat16_as_ushort(hx);
    h.y = ((uint32_t)__bfloat16_as_ushort(hw) << 16) | (uint32_t)__bfloat16_as_ushort(hz);
    l.x = bfpair(v.x - __bfloat162float(hx), v.y - __bfloat162float(hy));
    l.y = bfpair(v.z - __bfloat162float(hz), v.w - __bfloat162float(hw));
}
__device__ __forceinline__ void split1(float v, uint16_t &h, uint16_t &l) {
    __nv_bfloat16 hv = __float2bfloat16(v);
    h = __bfloat16_as_ushort(hv);
    l = __bfloat16_as_ushort(__float2bfloat16(v - __bfloat162float(hv)));
}
__device__ __forceinline__ void cpa(uint32_t s, const void* g) {
    asm volatile("cp.async.ca.shared.global [%0], [%1], 16;" :: "r"(s), "l"(g));
}
__device__ __forceinline__ void cpcommit() { asm volatile("cp.async.commit_group;"); }
template<int N> __device__ __forceinline__ void cpwait() {
    asm volatile("cp.async.wait_group %0;" :: "n"(N));
}

// ---------- presplit kernels ----------
__global__ void split_seq(const float4* __restrict__ src, long n4) {
    long i = (long)blockIdx.x * blockDim.x + threadIdx.x;
    if (i >= n4) return;
    uint2 h, l; split4(src[i], h, l);
    ((uint2*)g_xh)[i] = h;
    ((uint2*)g_xl)[i] = l;
}
__global__ void split_small(const float4* __restrict__ ew, const float4* __restrict__ dw,
                            const float4* __restrict__ mw) {
    int i = blockIdx.x * blockDim.x + threadIdx.x;
    if (i < 32768) {
        uint2 h, l; split4(ew[i], h, l);
        ((uint2*)g_ewh)[i] = h; ((uint2*)g_ewl)[i] = l;
    } else if (i < 65536) {
        int j = i - 32768;
        uint2 h, l; split4(dw[j], h, l);
        ((uint2*)g_dwh)[j] = h; ((uint2*)g_dwl)[j] = l;
    } else if (i < 69632) {
        int j = i - 65536;
        uint2 h, l; split4(mw[j], h, l);
        ((uint2*)g_mh)[j] = h; ((uint2*)g_ml)[j] = l;
    }
}

// ---------- fused main kernel ----------
__global__ __launch_bounds__(NTH, 1)
void mwm2(const float* __restrict__ enc_b_, const float* __restrict__ dec_b_,
          float* __restrict__ recon, float* __restrict__ att, float* __restrict__ memout)
{
    extern __shared__ char smem[];
    uint32_t sb;
    asm("{ .reg .u64 t; cvta.to.shared.u64 t, %1; cvt.u32.u64 %0, t; }" : "=r"(sb) : "l"(smem));
    const int tid = threadIdx.x, wid = tid >> 5, wm = wid & 3, wn = wid >> 2;
    const int rm = wm * 32;
    const long row0 = (long)blockIdx.x * 128;

    // ===================== GEMM1: E = tanh(X @ enc_w^T + b) =====================
    {
        FragC acc[2][4];
        #pragma unroll
        for (int t = 0; t < 2; t++)
            #pragma unroll
            for (int f = 0; f < 4; f++) wmma::fill_fragment(acc[t][f], 0.0f);

        { // prologue: chunk 0
            int r = tid >> 2, sg = tid & 3;
            cpa(sb + P_XH(0) + r * 80 + sg * 16, g_xh + (row0 + r) * 512 + sg * 8);
            cpa(sb + P_XL(0) + r * 80 + sg * 16, g_xl + (row0 + r) * 512 + sg * 8);
            #pragma unroll
            for (int i = 0; i < 2; i++) {
                int o = tid + i * NTH, wr = o >> 2, ws = o & 3;
                cpa(sb + P_WH(0) + wr * 80 + ws * 16, g_ewh + wr * 512 + ws * 8);
                cpa(sb + P_WL(0) + wr * 80 + ws * 16, g_ewl + wr * 512 + ws * 8);
            }
            cpcommit();
        }
        for (int kc = 0; kc < 16; kc++) {
            const int buf = kc & 1;
            if (kc < 15) {
                const int nb = buf ^ 1, kn = kc + 1;
                int r = tid >> 2, sg = tid & 3;
                cpa(sb + P_XH(nb) + r * 80 + sg * 16, g_xh + (row0 + r) * 512 + kn * 32 + sg * 8);
                cpa(sb + P_XL(nb) + r * 80 + sg * 16, g_xl + (row0 + r) * 512 + kn * 32 + sg * 8);
                #pragma unroll
                for (int i = 0; i < 2; i++) {
                    int o = tid + i * NTH, wr = o >> 2, ws = o & 3;
                    cpa(sb + P_WH(nb) + wr * 80 + ws * 16, g_ewh + wr * 512 + kn * 32 + ws * 8);
                    cpa(sb + P_WL(nb) + wr * 80 + ws * 16, g_ewl + wr * 512 + kn * 32 + ws * 8);
                }
                cpcommit();
                cpwait<1>();
            } else cpwait<0>();
            __syncthreads();
            const __nv_bfloat16* Xh = (const __nv_bfloat16*)(smem + P_XH(buf));
            const __nv_bfloat16* Xl = (const __nv_bfloat16*)(smem + P_XL(buf));
            const __nv_bfloat16* Wh = (const __nv_bfloat16*)(smem + P_WH(buf));
            const __nv_bfloat16* Wl = (const __nv_bfloat16*)(smem + P_WL(buf));
            #pragma unroll
            for (int ks = 0; ks < 2; ks++) {
                FragA ah[2], al[2];
                #pragma unroll
                for (int t = 0; t < 2; t++) {
                    wmma::load_matrix_sync(ah[t], Xh + (rm + 16 * t) * 40 + ks * 16, 40);
                    wmma::load_matrix_sync(al[t], Xl + (rm + 16 * t) * 40 + ks * 16, 40);
                }
                #pragma unroll
                for (int f = 0; f < 4; f++) {
                    FragBc bh, bl;
                    wmma::load_matrix_sync(bh, Wh + (wn * 64 + f * 16) * 40 + ks * 16, 40);
                    wmma::load_matrix_sync(bl, Wl + (wn * 64 + f * 16) * 40 + ks * 16, 40);
                    #pragma unroll
                    for (int t = 0; t < 2; t++) {
                        wmma::mma_sync(acc[t][f], ah[t], bh, acc[t][f]);
                        wmma::mma_sync(acc[t][f], ah[t], bl, acc[t][f]);
                        wmma::mma_sync(acc[t][f], al[t], bh, acc[t][f]);
                    }
                }
            }
            __syncthreads();
        }
        // epilogue: tanh + bias + split -> Eh/El
        float* stg = (float*)(smem + STG_O);
        __nv_bfloat16* Eh = (__nv_bfloat16*)(smem + EH_O);
        __nv_bfloat16* El = (__nv_bfloat16*)(smem + EL_O);
        for (int f = 0; f < 4; f++) {
            #pragma unroll
            for (int t = 0; t < 2; t++)
                wmma::store_matrix_sync(stg + (rm + 16 * t) * 68 + wn * 16, acc[t][f], 68,
                                        wmma::mem_row_major);
            __syncthreads();
            #pragma unroll
            for (int i = 0; i < 16; i++) {
                int idx = tid + i * NTH, r = idx >> 6, c = idx & 63;
                int gn = (c >> 4) * 64 + f * 16 + (c & 15);
                float e = tanhf(stg[r * 68 + c] + __ldg(enc_b_ + gn));
                uint16_t h, l; split1(e, h, l);
                *(uint16_t*)(Eh + r * 264 + gn) = h;
                *(uint16_t*)(El + r * 264 + gn) = l;
            }
            __syncthreads();
        }
    }

    // ===================== GEMM2: logits = E @ mem^T =====================
    {
        const __nv_bfloat16* Eh = (const __nv_bfloat16*)(smem + EH_O);
        const __nv_bfloat16* El = (const __nv_bfloat16*)(smem + EL_O);
        FragC acc[2];
        wmma::fill_fragment(acc[0], 0.0f);
        wmma::fill_fragment(acc[1], 0.0f);
        for (int kh = 0; kh < 2; kh++) {
            #pragma unroll
            for (int i = 0; i < 2; i++) {
                int o = tid + i * NTH, r = o >> 4, sg = o & 15;
                cpa(sb + MKH_O + r * 272 + sg * 16, g_mh + r * 256 + kh * 128 + sg * 8);
                cpa(sb + MKL_O + r * 272 + sg * 16, g_ml + r * 256 + kh * 128 + sg * 8);
            }
            cpcommit(); cpwait<0>();
            __syncthreads();
            const __nv_bfloat16* MKh = (const __nv_bfloat16*)(smem + MKH_O);
            const __nv_bfloat16* MKl = (const __nv_bfloat16*)(smem + MKL_O);
            #pragma unroll
            for (int ks = 0; ks < 8; ks++) {
                FragA ah[2], al[2];
                #pragma unroll
                for (int t = 0; t < 2; t++) {
                    wmma::load_matrix_sync(ah[t], Eh + (rm + 16 * t) * 264 + kh * 128 + ks * 16, 264);
                    wmma::load_matrix_sync(al[t], El + (rm + 16 * t) * 264 + kh * 128 + ks * 16, 264);
                }
                FragBc bh, bl;
                wmma::load_matrix_sync(bh, MKh + (wn * 16) * 136 + ks * 16, 136);
                wmma::load_matrix_sync(bl, MKl + (wn * 16) * 136 + ks * 16, 136);
                #pragma unroll
                for (int t = 0; t < 2; t++) {
                    wmma::mma_sync(acc[t], ah[t], bh, acc[t]);
                    wmma::mma_sync(acc[t], ah[t], bl, acc[t]);
                    wmma::mma_sync(acc[t], al[t], bh, acc[t]);
                }
            }
            __syncthreads();
        }
        float* stg = (float*)(smem + STG_O);
        #pragma unroll
        for (int t = 0; t < 2; t++)
            wmma::store_matrix_sync(stg + (rm + 16 * t) * 68 + wn * 16, acc[t], 68,
                                    wmma::mem_row_major);
        __syncthreads();
    }

    // ------ prefetch GEMM3 B operand (overlaps softmax) ------
    #pragma unroll
    for (int i = 0; i < 4; i++) {
        int o = tid + i * NTH, r = o >> 5, sg = o & 31;
        cpa(sb + M3H_O + r * 528 + sg * 16, g_mh + r * 256 + sg * 8);
        cpa(sb + M3L_O + r * 528 + sg * 16, g_ml + r * 256 + sg * 8);
    }
    cpcommit();

    // ------ softmax (threads 0..127, one row each) ------
    {
        __nv_bfloat16* Ah = (__nv_bfloat16*)(smem + ATH_O);
        __nv_bfloat16* Al = (__nv_bfloat16*)(smem + ATL_O);
        if (tid < 128) {
            const float* lr = (const float*)(smem + STG_O) + tid * 68;
            float e[64], m = -1e30f;
            #pragma unroll
            for (int c = 0; c < 64; c++) { e[c] = lr[c]; m = fmaxf(m, e[c]); }
            float sum = 0.f;
            #pragma unroll
            for (int c = 0; c < 64; c++) { e[c] = __expf((e[c] - m) * 0.0625f); sum += e[c]; }
            float inv = 1.0f / sum;
            float* arow = att + (row0 + tid) * 64;
            #pragma unroll
            for (int c = 0; c < 64; c += 4)
                *(float4*)(arow + c) = make_float4(e[c] * inv, e[c+1] * inv,
                                                   e[c+2] * inv, e[c+3] * inv);
            #pragma unroll
            for (int c = 0; c < 64; c++) {
                uint16_t h, l; split1(e[c] * inv, h, l);
                *(uint16_t*)(Ah + tid * 72 + c) = h;
                *(uint16_t*)(Al + tid * 72 + c) = l;
            }
        }
        cpwait<0>();
        __syncthreads();
    }

    // ===================== GEMM3: M = attn @ mem =====================
    {
        const __nv_bfloat16* Ah  = (const __nv_bfloat16*)(smem + ATH_O);
        const __nv_bfloat16* Al  = (const __nv_bfloat16*)(smem + ATL_O);
        const __nv_bfloat16* M3h = (const __nv_bfloat16*)(smem + M3H_O);
        const __nv_bfloat16* M3l = (const __nv_bfloat16*)(smem + M3L_O);
        FragC acc[2][4];
        #pragma unroll
        for (int t = 0; t < 2; t++)
            #pragma unroll
            for (int f = 0; f < 4; f++) wmma::fill_fragment(acc[t][f], 0.0f);
        #pragma unroll
        for (int ks = 0; ks < 4; ks++) {
            FragA ah[2], al[2];
            #pragma unroll
            for (int t = 0; t < 2; t++) {
                wmma::load_matrix_sync(ah[t], Ah + (rm + 16 * t) * 72 + ks * 16, 72);
                wmma::load_matrix_sync(al[t], Al + (rm + 16 * t) * 72 + ks * 16, 72);
            }
            #pragma unroll
            for (int f = 0; f < 4; f++) {
                FragBr bh, bl;
                wmma::load_matrix_sync(bh, M3h + (ks * 16) * 264 + wn * 64 + f * 16, 264);
                wmma::load_matrix_sync(bl, M3l + (ks * 16) * 264 + wn * 64 + f * 16, 264);
                #pragma unroll
                for (int t = 0; t < 2; t++) {
                    wmma::mma_sync(acc[t][f], ah[t], bh, acc[t][f]);
                    wmma::mma_sync(acc[t][f], ah[t], bl, acc[t][f]);
                    wmma::mma_sync(acc[t][f], al[t], bh, acc[t][f]);
                }
            }
        }
        __syncthreads();
        float* stg = (float*)(smem + STG_O);
        __nv_bfloat16* Mh = (__nv_bfloat16*)(smem + MH_O);
        __nv_bfloat16* Ml = (__nv_bfloat16*)(smem + ML_O);
        for (int f = 0; f < 4; f++) {
            #pragma unroll
            for (int t = 0; t < 2; t++)
                wmma::store_matrix_sync(stg + (rm + 16 * t) * 68 + wn * 16, acc[t][f], 68,
                                        wmma::mem_row_major);
            __syncthreads();
            #pragma unroll
            for (int i = 0; i < 16; i++) {
                int idx = tid + i * NTH, r = idx >> 6, c = idx & 63;
                int gn = (c >> 4) * 64 + f * 16 + (c & 15);
                float v = stg[r * 68 + c];
                memout[(row0 + r) * 256 + gn] = v;
                uint16_t h, l; split1(v, h, l);
                *(uint16_t*)(Mh + r * 264 + gn) = h;
                *(uint16_t*)(Ml + r * 264 + gn) = l;
            }
            __syncthreads();
        }
    }

    // ===================== GEMM4: recon = M @ dec_w^T + dec_b =====================
    {
        const __nv_bfloat16* Mh = (const __nv_bfloat16*)(smem + MH_O);
        const __nv_bfloat16* Ml = (const __nv_bfloat16*)(smem + ML_O);
        float* stg = (float*)(smem + STG_O);
        for (int nt = 0; nt < 4; nt++) {
            FragC acc[2][2];
            #pragma unroll
            for (int t = 0; t < 2; t++)
                #pragma unroll
                for (int f = 0; f < 2; f++) wmma::fill_fragment(acc[t][f], 0.0f);
            { // prologue chunk 0
                int r = tid >> 2, sg = tid & 3;
                cpa(sb + B4H(0) + r * 80 + sg * 16, g_dwh + (nt * 128 + r) * 256 + sg * 8);
                cpa(sb + B4L(0) + r * 80 + sg * 16, g_dwl + (nt * 128 + r) * 256 + sg * 8);
                cpcommit();
            }
            for (int kc = 0; kc < 8; kc++) {
                const int buf = kc & 1;
                if (kc < 7) {
                    const int nb = buf ^ 1, kn = kc + 1;
                    int r = tid >> 2, sg = tid & 3;
                    cpa(sb + B4H(nb) + r * 80 + sg * 16,
                        g_dwh + (nt * 128 + r) * 256 + kn * 32 + sg * 8);
                    cpa(sb + B4L(nb) + r * 80 + sg * 16,
                        g_dwl + (nt * 128 + r) * 256 + kn * 32 + sg * 8);
                    cpcommit(); cpwait<1>();
                } else cpwait<0>();
                __syncthreads();
                const __nv_bfloat16* Bh = (const __nv_bfloat16*)(smem + B4H(buf));
                const __nv_bfloat16* Bl = (const __nv_bfloat16*)(smem + B4L(buf));
                #pragma unroll
                for (int ks = 0; ks < 2; ks++) {
                    FragA ah[2], al[2];
                    #pragma unroll
                    for (int t = 0; t < 2; t++) {
                        wmma::load_matrix_sync(ah[t], Mh + (rm + 16 * t) * 264 + kc * 32 + ks * 16, 264);
                        wmma::load_matrix_sync(al[t], Ml + (rm + 16 * t) * 264 + kc * 32 + ks * 16, 264);
                    }
                    #pragma unroll
                    for (int f = 0; f < 2; f++) {
                        FragBc bh, bl;
                        wmma::load_matrix_sync(bh, Bh + (wn * 32 + f * 16) * 40 + ks * 16, 40);
                        wmma::load_matrix_sync(bl, Bl + (wn * 32 + f * 16) * 40 + ks * 16, 40);
                        #pragma unroll
                        for (int t = 0; t < 2; t++) {
                            wmma::mma_sync(acc[t][f], ah[t], bh, acc[t][f]);
                            wmma::mma_sync(acc[t][f], ah[t], bl, acc[t][f]);
                            wmma::mma_sync(acc[t][f], al[t], bh, acc[t][f]);
                        }
                    }
                }
                __syncthreads();
            }
            for (int f = 0; f < 2; f++) {
                #pragma unroll
                for (int t = 0; t < 2; t++)
                    wmma::store_matrix_sync(stg + (rm + 16 * t) * 68 + wn * 16, acc[t][f], 68,
                                            wmma::mem_row_major);
                __syncthreads();
                #pragma unroll
                for (int i = 0; i < 16; i++) {
                    int idx = tid + i * NTH, r = idx >> 6, c = idx & 63;
                    int gn = (c >> 4) * 32 + f * 16 + (c & 15);
                    int d = nt * 128 + gn;
                    recon[(row0 + r) * 512 + d] = stg[r * 68 + c] + __ldg(dec_b_ + d);
                }
                __syncthreads();
            }
        }
    }
}

extern "C" void kernel_launch(void* const* d_in, const int* in_sizes, int n_in,
                              void* d_out, int out_size)
{
    const float* seq   = (const float*)d_in[0];
    const float* enc_w = (const float*)d_in[1];
    const float* enc_b = (const float*)d_in[2];
    const float* memw  = (const float*)d_in[3];
    const float* dec_w = (const float*)d_in[4];
    const float* dec_b = (const float*)d_in[5];

    const long R = (long)in_sizes[0] / 512;   // 65536

    float* out    = (float*)d_out;
    float* recon  = out;
    float* att    = out + R * 512;
    float* memout = att + R * 64;

    const long n4 = R * 128;   // float4 count of seq
    split_seq<<<(unsigned)((n4 + 255) / 256), 256>>>((const float4*)seq, n4);
    split_small<<<272, 256>>>((const float4*)enc_w, (const float4*)dec_w, (const float4*)memw);

    cudaFuncSetAttribute(mwm2, cudaFuncAttributeMaxDynamicSharedMemorySize, SMEM_TOTAL);
    mwm2<<<(unsigned)(R / 128), NTH, SMEM_TOTAL>>>(enc_b, dec_b, recon, att, memout);
}

// round 7
// speedup vs baseline: 1.6969x; 1.6969x over previous
#include <cuda_runtime.h>
#include <cuda_bf16.h>
#include <mma.h>
#include <stdint.h>
#include <math.h>
using namespace nvcuda;

#define NTH 256
#define RTOT 65536L

// Pre-split bf16 hi/lo copies of fp32 inputs
__device__ __nv_bfloat16 g_xh[RTOT * 512], g_xl[RTOT * 512];
__device__ __nv_bfloat16 g_ewh[256 * 512], g_ewl[256 * 512];
__device__ __nv_bfloat16 g_dwh[512 * 256], g_dwl[512 * 256];
__device__ __nv_bfloat16 g_mh[64 * 256],  g_ml[64 * 256];

// ---- smem map (bytes). Phase-unioned regions, total 108544 (2 CTAs/SM). ----
// [0,20480):     GEMM1 X chunks | stg f32 [64][68] | B4 buf0 (h@0,l@10240)
// [20480,102400):GEMM1 W chunks | mem tile [64][264] h/l | M tiles h/l
// [88064,108544):E blk tiles | attn tiles | M-stg | B4 buf1 (h@88064,l@98304)
#define XH(b)  ((b) * 10240)
#define XL(b)  ((b) * 10240 + 5120)
#define WH(b)  (20480 + (b) * 40960)
#define WL(b)  (40960 + (b) * 40960)
#define STG_O  0
#define MEMH_O 20480
#define MEML_O 54272
#define EBH_O  88064
#define EBL_O  97280
#define ATH_O  88064
#define ATL_O  97280
#define MSTG_O 88064
#define MH_O   20480
#define ML_O   54272
#define B4H(b) ((b) ? 88064 : 0)
#define B4L(b) ((b) ? 98304 : 10240)
#define SMEM_TOTAL 108544

typedef wmma::fragment<wmma::matrix_a, 16,16,16, __nv_bfloat16, wmma::row_major> FragA;
typedef wmma::fragment<wmma::matrix_b, 16,16,16, __nv_bfloat16, wmma::col_major> FragBc;
typedef wmma::fragment<wmma::matrix_b, 16,16,16, __nv_bfloat16, wmma::row_major> FragBr;
typedef wmma::fragment<wmma::accumulator, 16,16,16, float> FragC;

__device__ __forceinline__ uint32_t bfpair(float a, float b) {
    __nv_bfloat162 t = __floats2bfloat162_rn(a, b);
    return *reinterpret_cast<uint32_t*>(&t);
}
__device__ __forceinline__ void split4(const float4 v, uint2 &h, uint2 &l) {
    __nv_bfloat16 hx = __float2bfloat16(v.x), hy = __float2bfloat16(v.y);
    __nv_bfloat16 hz = __float2bfloat16(v.z), hw = __float2bfloat16(v.w);
    h.x = ((uint32_t)__bfloat16_as_ushort(hy) << 16) | (uint32_t)__bfloat16_as_ushort(hx);
    h.y = ((uint32_t)__bfloat16_as_ushort(hw) << 16) | (uint32_t)__bfloat16_as_ushort(hz);
    l.x = bfpair(v.x - __bfloat162float(hx), v.y - __bfloat162float(hy));
    l.y = bfpair(v.z - __bfloat162float(hz), v.w - __bfloat162float(hw));
}
__device__ __forceinline__ void split1(float v, uint16_t &h, uint16_t &l) {
    __nv_bfloat16 hv = __float2bfloat16(v);
    h = __bfloat16_as_ushort(hv);
    l = __bfloat16_as_ushort(__float2bfloat16(v - __bfloat162float(hv)));
}
__device__ __forceinline__ void cpa(uint32_t s, const void* g) {
    asm volatile("cp.async.ca.shared.global [%0], [%1], 16;" :: "r"(s), "l"(g));
}
__device__ __forceinline__ void cpcommit() { asm volatile("cp.async.commit_group;"); }
template<int N> __device__ __forceinline__ void cpwait() {
    asm volatile("cp.async.wait_group %0;" :: "n"(N));
}

__global__ void split_seq(const float4* __restrict__ src, long n4) {
    long i = (long)blockIdx.x * blockDim.x + threadIdx.x;
    if (i >= n4) return;
    uint2 h, l; split4(src[i], h, l);
    ((uint2*)g_xh)[i] = h;
    ((uint2*)g_xl)[i] = l;
}
__global__ void split_small(const float4* __restrict__ ew, const float4* __restrict__ dw,
                            const float4* __restrict__ mw) {
    int i = blockIdx.x * blockDim.x + threadIdx.x;
    if (i < 32768) {
        uint2 h, l; split4(ew[i], h, l);
        ((uint2*)g_ewh)[i] = h; ((uint2*)g_ewl)[i] = l;
    } else if (i < 65536) {
        int j = i - 32768;
        uint2 h, l; split4(dw[j], h, l);
        ((uint2*)g_dwh)[j] = h; ((uint2*)g_dwl)[j] = l;
    } else if (i < 69632) {
        int j = i - 65536;
        uint2 h, l; split4(mw[j], h, l);
        ((uint2*)g_mh)[j] = h; ((uint2*)g_ml)[j] = l;
    }
}

__global__ __launch_bounds__(NTH, 2)
void mwm3(const float* __restrict__ enc_b_, const float* __restrict__ dec_b_,
          float* __restrict__ recon, float* __restrict__ att, float* __restrict__ memout)
{
    extern __shared__ char smem[];
    uint32_t sb;
    asm("{ .reg .u64 t; cvta.to.shared.u64 t, %1; cvt.u32.u64 %0, t; }" : "=r"(sb) : "l"(smem));
    const int tid = threadIdx.x, wid = tid >> 5;
    const int wm = wid & 1, wn = wid >> 1;     // 2 x 4 warp grid
    const int rm = wm * 32;
    const long row0 = (long)blockIdx.x * 64;

    // ================== GEMM1 mainloop: Cpre = X @ enc_w^T ==================
    FragC acc1[2][4];                           // rows rm+32, cols wn*64..+63
    #pragma unroll
    for (int t = 0; t < 2; t++)
        #pragma unroll
        for (int f = 0; f < 4; f++) wmma::fill_fragment(acc1[t][f], 0.0f);

    { // prologue chunk 0
        int r = tid >> 2, sg = tid & 3;
        cpa(sb + XH(0) + r * 80 + sg * 16, g_xh + (row0 + r) * 512 + sg * 8);
        cpa(sb + XL(0) + r * 80 + sg * 16, g_xl + (row0 + r) * 512 + sg * 8);
        #pragma unroll
        for (int i = 0; i < 4; i++) {
            int o = tid + i * NTH, wr = o >> 2, ws = o & 3;
            cpa(sb + WH(0) + wr * 80 + ws * 16, g_ewh + wr * 512 + ws * 8);
            cpa(sb + WL(0) + wr * 80 + ws * 16, g_ewl + wr * 512 + ws * 8);
        }
        cpcommit();
    }
    for (int kc = 0; kc < 16; kc++) {
        const int buf = kc & 1;
        if (kc < 15) {
            const int nb = buf ^ 1, kn = kc + 1;
            int r = tid >> 2, sg = tid & 3;
            cpa(sb + XH(nb) + r * 80 + sg * 16, g_xh + (row0 + r) * 512 + kn * 32 + sg * 8);
            cpa(sb + XL(nb) + r * 80 + sg * 16, g_xl + (row0 + r) * 512 + kn * 32 + sg * 8);
            #pragma unroll
            for (int i = 0; i < 4; i++) {
                int o = tid + i * NTH, wr = o >> 2, ws = o & 3;
                cpa(sb + WH(nb) + wr * 80 + ws * 16, g_ewh + wr * 512 + kn * 32 + ws * 8);
                cpa(sb + WL(nb) + wr * 80 + ws * 16, g_ewl + wr * 512 + kn * 32 + ws * 8);
            }
            cpcommit(); cpwait<1>();
        } else cpwait<0>();
        __syncthreads();
        const __nv_bfloat16* Xh = (const __nv_bfloat16*)(smem + XH(buf));
        const __nv_bfloat16* Xl = (const __nv_bfloat16*)(smem + XL(buf));
        const __nv_bfloat16* Wh = (const __nv_bfloat16*)(smem + WH(buf));
        const __nv_bfloat16* Wl = (const __nv_bfloat16*)(smem + WL(buf));
        #pragma unroll
        for (int ks = 0; ks < 2; ks++) {
            FragA ah[2], al[2];
            #pragma unroll
            for (int t = 0; t < 2; t++) {
                wmma::load_matrix_sync(ah[t], Xh + (rm + 16 * t) * 40 + ks * 16, 40);
                wmma::load_matrix_sync(al[t], Xl + (rm + 16 * t) * 40 + ks * 16, 40);
            }
            #pragma unroll
            for (int f = 0; f < 4; f++) {
                FragBc bh, bl;
                wmma::load_matrix_sync(bh, Wh + (wn * 64 + f * 16) * 40 + ks * 16, 40);
                wmma::load_matrix_sync(bl, Wl + (wn * 64 + f * 16) * 40 + ks * 16, 40);
                #pragma unroll
                for (int t = 0; t < 2; t++) {
                    wmma::mma_sync(acc1[t][f], ah[t], bh, acc1[t][f]);
                    wmma::mma_sync(acc1[t][f], ah[t], bl, acc1[t][f]);
                    wmma::mma_sync(acc1[t][f], al[t], bh, acc1[t][f]);
                }
            }
        }
        __syncthreads();
    }

    // ---- load memory bank tile [64][264] h/l (serves GEMM2 col-major AND GEMM3 row-major)
    #pragma unroll
    for (int i = 0; i < 8; i++) {
        int o = tid + i * NTH, s = o >> 5, c8 = o & 31;
        cpa(sb + MEMH_O + s * 528 + c8 * 16, g_mh + s * 256 + c8 * 8);
        cpa(sb + MEML_O + s * 528 + c8 * 16, g_ml + s * 256 + c8 * 8);
    }
    cpcommit();

    // ====== GEMM1 epilogue fused with GEMM2: per 64-col block b ======
    FragC acc2[2];                              // logits rows rm+32, slots wn*16..+15
    wmma::fill_fragment(acc2[0], 0.0f);
    wmma::fill_fragment(acc2[1], 0.0f);
    {
        float* stg = (float*)(smem + STG_O);
        __nv_bfloat16* Ebh = (__nv_bfloat16*)(smem + EBH_O);
        __nv_bfloat16* Ebl = (__nv_bfloat16*)(smem + EBL_O);
        const __nv_bfloat16* Mh = (const __nv_bfloat16*)(smem + MEMH_O);
        const __nv_bfloat16* Ml = (const __nv_bfloat16*)(smem + MEML_O);
        for (int b = 0; b < 4; b++) {
            if (wn == b)
                #pragma unroll
                for (int t = 0; t < 2; t++)
                    #pragma unroll
                    for (int f = 0; f < 4; f++)
                        wmma::store_matrix_sync(stg + (rm + 16 * t) * 68 + f * 16,
                                                acc1[t][f], 68, wmma::mem_row_major);
            __syncthreads();
            #pragma unroll
            for (int i = 0; i < 16; i++) {
                int idx = tid + i * NTH, r = idx >> 6, c = idx & 63;
                float e = tanhf(stg[r * 68 + c] + __ldg(enc_b_ + b * 64 + c));
                uint16_t h, l; split1(e, h, l);
                Ebh[r * 72 + c] = __ushort_as_bfloat16(h);
                Ebl[r * 72 + c] = __ushort_as_bfloat16(l);
            }
            if (b == 0) cpwait<0>();
            __syncthreads();
            #pragma unroll
            for (int ks = 0; ks < 4; ks++) {
                FragA ah[2], al[2];
                #pragma unroll
                for (int t = 0; t < 2; t++) {
                    wmma::load_matrix_sync(ah[t], Ebh + (rm + 16 * t) * 72 + ks * 16, 72);
                    wmma::load_matrix_sync(al[t], Ebl + (rm + 16 * t) * 72 + ks * 16, 72);
                }
                FragBc bh, bl;
                wmma::load_matrix_sync(bh, Mh + (wn * 16) * 264 + b * 64 + ks * 16, 264);
                wmma::load_matrix_sync(bl, Ml + (wn * 16) * 264 + b * 64 + ks * 16, 264);
                #pragma unroll
                for (int t = 0; t < 2; t++) {
                    wmma::mma_sync(acc2[t], ah[t], bh, acc2[t]);
                    wmma::mma_sync(acc2[t], ah[t], bl, acc2[t]);
                    wmma::mma_sync(acc2[t], al[t], bh, acc2[t]);
                }
            }
            __syncthreads();
        }
        // logits -> stg
        #pragma unroll
        for (int t = 0; t < 2; t++)
            wmma::store_matrix_sync(stg + (rm + 16 * t) * 68 + wn * 16, acc2[t], 68,
                                    wmma::mem_row_major);
        __syncthreads();
    }

    // ====== softmax (threads 0..63, one row each) + attn tiles ======
    {
        __nv_bfloat16* Ah = (__nv_bfloat16*)(smem + ATH_O);
        __nv_bfloat16* Al = (__nv_bfloat16*)(smem + ATL_O);
        if (tid < 64) {
            float* lr = (float*)(smem + STG_O) + tid * 68;
            float m = -1e30f;
            #pragma unroll
            for (int c = 0; c < 64; c++) m = fmaxf(m, lr[c]);
            float sum = 0.f;
            #pragma unroll
            for (int c = 0; c < 64; c++) {
                float e = __expf((lr[c] - m) * 0.0625f);
                lr[c] = e; sum += e;
            }
            float inv = 1.0f / sum;
            float* arow = att + (row0 + tid) * 64;
            #pragma unroll
            for (int c = 0; c < 64; c += 4) {
                float4 v = *(float4*)(lr + c);
                v.x *= inv; v.y *= inv; v.z *= inv; v.w *= inv;
                *(float4*)(arow + c) = v;
                uint16_t h, l;
                split1(v.x, h, l); Ah[tid*72+c]   = __ushort_as_bfloat16(h); Al[tid*72+c]   = __ushort_as_bfloat16(l);
                split1(v.y, h, l); Ah[tid*72+c+1] = __ushort_as_bfloat16(h); Al[tid*72+c+1] = __ushort_as_bfloat16(l);
                split1(v.z, h, l); Ah[tid*72+c+2] = __ushort_as_bfloat16(h); Al[tid*72+c+2] = __ushort_as_bfloat16(l);
                split1(v.w, h, l); Ah[tid*72+c+3] = __ushort_as_bfloat16(h); Al[tid*72+c+3] = __ushort_as_bfloat16(l);
            }
        }
        __syncthreads();
    }

    // ---- prefetch GEMM4 chunk q=0 into buf0 (region @0 now dead) ----
    #pragma unroll
    for (int i = 0; i < 2; i++) {
        int o = tid + i * NTH, r = o >> 2, sg = o & 3;
        cpa(sb + B4H(0) + r * 80 + sg * 16, g_dwh + r * 256 + sg * 8);
        cpa(sb + B4L(0) + r * 80 + sg * 16, g_dwl + r * 256 + sg * 8);
    }
    cpcommit();

    // ================== GEMM3: M = attn @ mem ==================
    FragC acc3[2][4];
    #pragma unroll
    for (int t = 0; t < 2; t++)
        #pragma unroll
        for (int f = 0; f < 4; f++) wmma::fill_fragment(acc3[t][f], 0.0f);
    {
        const __nv_bfloat16* Ah = (const __nv_bfloat16*)(smem + ATH_O);
        const __nv_bfloat16* Al = (const __nv_bfloat16*)(smem + ATL_O);
        const __nv_bfloat16* Mh = (const __nv_bfloat16*)(smem + MEMH_O);
        const __nv_bfloat16* Ml = (const __nv_bfloat16*)(smem + MEML_O);
        #pragma unroll
        for (int ks = 0; ks < 4; ks++) {
            FragA ah[2], al[2];
            #pragma unroll
            for (int t = 0; t < 2; t++) {
                wmma::load_matrix_sync(ah[t], Ah + (rm + 16 * t) * 72 + ks * 16, 72);
                wmma::load_matrix_sync(al[t], Al + (rm + 16 * t) * 72 + ks * 16, 72);
            }
            #pragma unroll
            for (int f = 0; f < 4; f++) {
                FragBr bh, bl;
                wmma::load_matrix_sync(bh, Mh + (ks * 16) * 264 + wn * 64 + f * 16, 264);
                wmma::load_matrix_sync(bl, Ml + (ks * 16) * 264 + wn * 64 + f * 16, 264);
                #pragma unroll
                for (int t = 0; t < 2; t++) {
                    wmma::mma_sync(acc3[t][f], ah[t], bh, acc3[t][f]);
                    wmma::mma_sync(acc3[t][f], ah[t], bl, acc3[t][f]);
                    wmma::mma_sync(acc3[t][f], al[t], bh, acc3[t][f]);
                }
            }
        }
    }
    __syncthreads();   // mem + attn tiles dead

    // ---- M epilogue: memout + M tiles (h/l) ----
    {
        float* stg = (float*)(smem + MSTG_O);
        __nv_bfloat16* Mh = (__nv_bfloat16*)(smem + MH_O);
        __nv_bfloat16* Ml = (__nv_bfloat16*)(smem + ML_O);
        for (int q = 0; q < 4; q++) {
            if (wn == q)
                #pragma unroll
                for (int t = 0; t < 2; t++)
                    #pragma unroll
                    for (int f = 0; f < 4; f++)
                        wmma::store_matrix_sync(stg + (rm + 16 * t) * 68 + f * 16,
                                                acc3[t][f], 68, wmma::mem_row_major);
            __syncthreads();
            #pragma unroll
            for (int i = 0; i < 16; i++) {
                int idx = tid + i * NTH, r = idx >> 6, c = idx & 63;
                int gn = q * 64 + c;
                float v = stg[r * 68 + c];
                memout[(row0 + r) * 256 + gn] = v;
                uint16_t h, l; split1(v, h, l);
                Mh[r * 264 + gn] = __ushort_as_bfloat16(h);
                Ml[r * 264 + gn] = __ushort_as_bfloat16(l);
            }
            __syncthreads();
        }
    }

    // ================== GEMM4: recon = M @ dec_w^T + dec_b ==================
    {
        const __nv_bfloat16* Mh = (const __nv_bfloat16*)(smem + MH_O);
        const __nv_bfloat16* Ml = (const __nv_bfloat16*)(smem + ML_O);
        FragC acc4[2][2];
        for (int q = 0; q < 32; q++) {
            const int nt = q >> 3, kc = q & 7, buf = q & 1;
            if (kc == 0) {
                #pragma unroll
                for (int t = 0; t < 2; t++)
                    #pragma unroll
                    for (int f = 0; f < 2; f++) wmma::fill_fragment(acc4[t][f], 0.0f);
            }
            if (q < 31) {
                const int qp = q + 1, ntn = qp >> 3, kcn = qp & 7, nb = buf ^ 1;
                #pragma unroll
                for (int i = 0; i < 2; i++) {
                    int o = tid + i * NTH, r = o >> 2, sg = o & 3;
                    cpa(sb + B4H(nb) + r * 80 + sg * 16,
                        g_dwh + (ntn * 128 + r) * 256 + kcn * 32 + sg * 8);
                    cpa(sb + B4L(nb) + r * 80 + sg * 16,
                        g_dwl + (ntn * 128 + r) * 256 + kcn * 32 + sg * 8);
                }
                cpcommit(); cpwait<1>();
            } else cpwait<0>();
            __syncthreads();
            const __nv_bfloat16* Bh = (const __nv_bfloat16*)(smem + B4H(buf));
            const __nv_bfloat16* Bl = (const __nv_bfloat16*)(smem + B4L(buf));
            #pragma unroll
            for (int ks = 0; ks < 2; ks++) {
                FragA ah[2], al[2];
                #pragma unroll
                for (int t = 0; t < 2; t++) {
                    wmma::load_matrix_sync(ah[t], Mh + (rm + 16 * t) * 264 + kc * 32 + ks * 16, 264);
                    wmma::load_matrix_sync(al[t], Ml + (rm + 16 * t) * 264 + kc * 32 + ks * 16, 264);
                }
                #pragma unroll
                for (int f = 0; f < 2; f++) {
                    FragBc bh, bl;
                    wmma::load_matrix_sync(bh, Bh + (wn * 32 + f * 16) * 40 + ks * 16, 40);
                    wmma::load_matrix_sync(bl, Bl + (wn * 32 + f * 16) * 40 + ks * 16, 40);
                    #pragma unroll
                    for (int t = 0; t < 2; t++) {
                        wmma::mma_sync(acc4[t][f], ah[t], bh, acc4[t][f]);
                        wmma::mma_sync(acc4[t][f], ah[t], bl, acc4[t][f]);
                        wmma::mma_sync(acc4[t][f], al[t], bh, acc4[t][f]);
                    }
                }
            }
            __syncthreads();
            if (kc == 7) {   // nt epilogue; consumed buf is buf1 -> stage @MSTG_O
                float* stg = (float*)(smem + MSTG_O);
                for (int f = 0; f < 2; f++) {
                    #pragma unroll
                    for (int t = 0; t < 2; t++)
                        wmma::store_matrix_sync(stg + (rm + 16 * t) * 68 + wn * 16,
                                                acc4[t][f], 68, wmma::mem_row_major);
                    __syncthreads();
                    #pragma unroll
                    for (int i = 0; i < 16; i++) {
                        int idx = tid + i * NTH, r = idx >> 6, c = idx & 63;
                        int gn = (c >> 4) * 32 + f * 16 + (c & 15);
                        int d = nt * 128 + gn;
                        recon[(row0 + r) * 512 + d] = stg[r * 68 + c] + __ldg(dec_b_ + d);
                    }
                    __syncthreads();
                }
            }
        }
    }
}

extern "C" void kernel_launch(void* const* d_in, const int* in_sizes, int n_in,
                              void* d_out, int out_size)
{
    const float* seq   = (const float*)d_in[0];
    const float* enc_w = (const float*)d_in[1];
    const float* enc_b = (const float*)d_in[2];
    const float* memw  = (const float*)d_in[3];
    const float* dec_w = (const float*)d_in[4];
    const float* dec_b = (const float*)d_in[5];

    const long R = (long)in_sizes[0] / 512;   // 65536

    float* out    = (float*)d_out;
    float* recon  = out;
    float* att    = out + R * 512;
    float* memout = att + R * 64;

    const long n4 = R * 128;
    split_seq<<<(unsigned)((n4 + 255) / 256), 256>>>((const float4*)seq, n4);
    split_small<<<272, 256>>>((const float4*)enc_w, (const float4*)dec_w, (const float4*)memw);

    cudaFuncSetAttribute(mwm3, cudaFuncAttributeMaxDynamicSharedMemorySize, SMEM_TOTAL);
    mwm3<<<(unsigned)(R / 64), NTH, SMEM_TOTAL>>>(enc_b, dec_b, recon, att, memout);
}

// round 8
// speedup vs baseline: 1.9161x; 1.1292x over previous
#include <cuda_runtime.h>
#include <cuda_bf16.h>
#include <mma.h>
#include <stdint.h>
#include <math.h>
using namespace nvcuda;

#define NTH 256

// Pre-split bf16 hi/lo copies of the small fp32 inputs (weights + memory bank)
__device__ __nv_bfloat16 g_ewh[256 * 512], g_ewl[256 * 512];
__device__ __nv_bfloat16 g_dwh[512 * 256], g_dwl[512 * 256];
__device__ __nv_bfloat16 g_mh[64 * 256],  g_ml[64 * 256];

// ---- smem map (bytes). Phase-unioned regions, total 108544 (2 CTAs/SM). ----
#define XH(b)  ((b) * 10240)
#define XL(b)  ((b) * 10240 + 5120)
#define WH(b)  (20480 + (b) * 40960)
#define WL(b)  (40960 + (b) * 40960)
#define STG_O  0
#define MEMH_O 20480
#define MEML_O 54272
#define EBH_O  88064
#define EBL_O  97280
#define ATH_O  88064
#define ATL_O  97280
#define MSTG_O 88064
#define MH_O   20480
#define ML_O   54272
#define B4H(b) ((b) ? 88064 : 0)
#define B4L(b) ((b) ? 98304 : 10240)
#define SMEM_TOTAL 108544

typedef wmma::fragment<wmma::matrix_a, 16,16,16, __nv_bfloat16, wmma::row_major> FragA;
typedef wmma::fragment<wmma::matrix_b, 16,16,16, __nv_bfloat16, wmma::col_major> FragBc;
typedef wmma::fragment<wmma::matrix_b, 16,16,16, __nv_bfloat16, wmma::row_major> FragBr;
typedef wmma::fragment<wmma::accumulator, 16,16,16, float> FragC;

__device__ __forceinline__ uint32_t bfpair(float a, float b) {
    __nv_bfloat162 t = __floats2bfloat162_rn(a, b);
    return *reinterpret_cast<uint32_t*>(&t);
}
__device__ __forceinline__ void split4(const float4 v, uint2 &h, uint2 &l) {
    __nv_bfloat16 hx = __float2bfloat16(v.x), hy = __float2bfloat16(v.y);
    __nv_bfloat16 hz = __float2bfloat16(v.z), hw = __float2bfloat16(v.w);
    h.x = ((uint32_t)__bfloat16_as_ushort(hy) << 16) | (uint32_t)__bfloat16_as_ushort(hx);
    h.y = ((uint32_t)__bfloat16_as_ushort(hw) << 16) | (uint32_t)__bfloat16_as_ushort(hz);
    l.x = bfpair(v.x - __bfloat162float(hx), v.y - __bfloat162float(hy));
    l.y = bfpair(v.z - __bfloat162float(hz), v.w - __bfloat162float(hw));
}
__device__ __forceinline__ void split1(float v, uint16_t &h, uint16_t &l) {
    __nv_bfloat16 hv = __float2bfloat16(v);
    h = __bfloat16_as_ushort(hv);
    l = __bfloat16_as_ushort(__float2bfloat16(v - __bfloat162float(hv)));
}
__device__ __forceinline__ void cpa(uint32_t s, const void* g) {
    asm volatile("cp.async.ca.shared.global [%0], [%1], 16;" :: "r"(s), "l"(g));
}
__device__ __forceinline__ void cpcommit() { asm volatile("cp.async.commit_group;"); }
template<int N> __device__ __forceinline__ void cpwait() {
    asm volatile("cp.async.wait_group %0;" :: "n"(N));
}

__global__ void split_small(const float4* __restrict__ ew, const float4* __restrict__ dw,
                            const float4* __restrict__ mw) {
    int i = blockIdx.x * blockDim.x + threadIdx.x;
    if (i < 32768) {
        uint2 h, l; split4(ew[i], h, l);
        ((uint2*)g_ewh)[i] = h; ((uint2*)g_ewl)[i] = l;
    } else if (i < 65536) {
        int j = i - 32768;
        uint2 h, l; split4(dw[j], h, l);
        ((uint2*)g_dwh)[j] = h; ((uint2*)g_dwl)[j] = l;
    } else if (i < 69632) {
        int j = i - 65536;
        uint2 h, l; split4(mw[j], h, l);
        ((uint2*)g_mh)[j] = h; ((uint2*)g_ml)[j] = l;
    }
}

__global__ __launch_bounds__(NTH, 2)
void mwm4(const float* __restrict__ seq,
          const float* __restrict__ enc_b_, const float* __restrict__ dec_b_,
          float* __restrict__ recon, float* __restrict__ att, float* __restrict__ memout)
{
    extern __shared__ char smem[];
    uint32_t sb;
    asm("{ .reg .u64 t; cvta.to.shared.u64 t, %1; cvt.u32.u64 %0, t; }" : "=r"(sb) : "l"(smem));
    const int tid = threadIdx.x, wid = tid >> 5;
    const int wm = wid & 1, wn = wid >> 1;     // 2 x 4 warp grid
    const int rm = wm * 32;
    const long row0 = (long)blockIdx.x * 64;

    // X register pipeline: this thread's 8 f32 of each [64 rows][32 k] chunk
    const int xr = tid >> 2, xq = (tid & 3) * 8;
    const float* xsrc = seq + (row0 + xr) * 512 + xq;

    // convert chunk held in rx -> XH/XL(b)
    auto xconv = [&](float4* rx, int b) {
        uint2 h0, l0, h1, l1;
        split4(rx[0], h0, l0);
        split4(rx[1], h1, l1);
        __nv_bfloat16* Xh = (__nv_bfloat16*)(smem + XH(b));
        __nv_bfloat16* Xl = (__nv_bfloat16*)(smem + XL(b));
        *(uint2*)(Xh + xr * 40 + xq)     = h0;
        *(uint2*)(Xh + xr * 40 + xq + 4) = h1;
        *(uint2*)(Xl + xr * 40 + xq)     = l0;
        *(uint2*)(Xl + xr * 40 + xq + 4) = l1;
    };

    // ================== GEMM1 mainloop: Cpre = X @ enc_w^T ==================
    FragC acc1[2][4];
    #pragma unroll
    for (int t = 0; t < 2; t++)
        #pragma unroll
        for (int f = 0; f < 4; f++) wmma::fill_fragment(acc1[t][f], 0.0f);

    float4 rx[2][2];
    { // prologue: chunks 0,1 -> regs; convert chunk0; prefetch W chunk0
        rx[0][0] = *(const float4*)(xsrc);
        rx[0][1] = *(const float4*)(xsrc + 4);
        rx[1][0] = *(const float4*)(xsrc + 32);
        rx[1][1] = *(const float4*)(xsrc + 36);
        xconv(rx[0], 0);
        #pragma unroll
        for (int i = 0; i < 4; i++) {
            int o = tid + i * NTH, wr = o >> 2, ws = o & 3;
            cpa(sb + WH(0) + wr * 80 + ws * 16, g_ewh + wr * 512 + ws * 8);
            cpa(sb + WL(0) + wr * 80 + ws * 16, g_ewl + wr * 512 + ws * 8);
        }
        cpcommit();
    }
    for (int kc = 0; kc < 16; kc++) {
        const int buf = kc & 1;
        if (kc < 15) {
            const int nb = buf ^ 1, kn = kc + 1;
            #pragma unroll
            for (int i = 0; i < 4; i++) {
                int o = tid + i * NTH, wr = o >> 2, ws = o & 3;
                cpa(sb + WH(nb) + wr * 80 + ws * 16, g_ewh + wr * 512 + kn * 32 + ws * 8);
                cpa(sb + WL(nb) + wr * 80 + ws * 16, g_ewl + wr * 512 + kn * 32 + ws * 8);
            }
            cpcommit();
            xconv(rx[nb], nb);                     // chunk kc+1 -> XH(nb)
            if (kc < 14) {                          // LDG chunk kc+2 -> rx[buf]
                rx[buf][0] = *(const float4*)(xsrc + (kc + 2) * 32);
                rx[buf][1] = *(const float4*)(xsrc + (kc + 2) * 32 + 4);
            }
            cpwait<1>();
        } else cpwait<0>();
        __syncthreads();
        const __nv_bfloat16* Xh = (const __nv_bfloat16*)(smem + XH(buf));
        const __nv_bfloat16* Xl = (const __nv_bfloat16*)(smem + XL(buf));
        const __nv_bfloat16* Wh = (const __nv_bfloat16*)(smem + WH(buf));
        const __nv_bfloat16* Wl = (const __nv_bfloat16*)(smem + WL(buf));
        #pragma unroll
        for (int ks = 0; ks < 2; ks++) {
            FragA ah[2], al[2];
            #pragma unroll
            for (int t = 0; t < 2; t++) {
                wmma::load_matrix_sync(ah[t], Xh + (rm + 16 * t) * 40 + ks * 16, 40);
                wmma::load_matrix_sync(al[t], Xl + (rm + 16 * t) * 40 + ks * 16, 40);
            }
            #pragma unroll
            for (int f = 0; f < 4; f++) {
                FragBc bh, bl;
                wmma::load_matrix_sync(bh, Wh + (wn * 64 + f * 16) * 40 + ks * 16, 40);
                wmma::load_matrix_sync(bl, Wl + (wn * 64 + f * 16) * 40 + ks * 16, 40);
                #pragma unroll
                for (int t = 0; t < 2; t++) {
                    wmma::mma_sync(acc1[t][f], ah[t], bh, acc1[t][f]);
                    wmma::mma_sync(acc1[t][f], ah[t], bl, acc1[t][f]);
                    wmma::mma_sync(acc1[t][f], al[t], bh, acc1[t][f]);
                }
            }
        }
        __syncthreads();
    }

    // ---- load memory bank tile [64][264] h/l ----
    #pragma unroll
    for (int i = 0; i < 8; i++) {
        int o = tid + i * NTH, s = o >> 5, c8 = o & 31;
        cpa(sb + MEMH_O + s * 528 + c8 * 16, g_mh + s * 256 + c8 * 8);
        cpa(sb + MEML_O + s * 528 + c8 * 16, g_ml + s * 256 + c8 * 8);
    }
    cpcommit();

    // ====== GEMM1 epilogue fused with GEMM2 ======
    FragC acc2[2];
    wmma::fill_fragment(acc2[0], 0.0f);
    wmma::fill_fragment(acc2[1], 0.0f);
    {
        float* stg = (float*)(smem + STG_O);
        __nv_bfloat16* Ebh = (__nv_bfloat16*)(smem + EBH_O);
        __nv_bfloat16* Ebl = (__nv_bfloat16*)(smem + EBL_O);
        const __nv_bfloat16* Mh = (const __nv_bfloat16*)(smem + MEMH_O);
        const __nv_bfloat16* Ml = (const __nv_bfloat16*)(smem + MEML_O);
        for (int b = 0; b < 4; b++) {
            if (wn == b)
                #pragma unroll
                for (int t = 0; t < 2; t++)
                    #pragma unroll
                    for (int f = 0; f < 4; f++)
                        wmma::store_matrix_sync(stg + (rm + 16 * t) * 68 + f * 16,
                                                acc1[t][f], 68, wmma::mem_row_major);
            __syncthreads();
            #pragma unroll
            for (int i = 0; i < 16; i++) {
                int idx = tid + i * NTH, r = idx >> 6, c = idx & 63;
                float e = tanhf(stg[r * 68 + c] + __ldg(enc_b_ + b * 64 + c));
                uint16_t h, l; split1(e, h, l);
                Ebh[r * 72 + c] = __ushort_as_bfloat16(h);
                Ebl[r * 72 + c] = __ushort_as_bfloat16(l);
            }
            if (b == 0) cpwait<0>();
            __syncthreads();
            #pragma unroll
            for (int ks = 0; ks < 4; ks++) {
                FragA ah[2], al[2];
                #pragma unroll
                for (int t = 0; t < 2; t++) {
                    wmma::load_matrix_sync(ah[t], Ebh + (rm + 16 * t) * 72 + ks * 16, 72);
                    wmma::load_matrix_sync(al[t], Ebl + (rm + 16 * t) * 72 + ks * 16, 72);
                }
                FragBc bh, bl;
                wmma::load_matrix_sync(bh, Mh + (wn * 16) * 264 + b * 64 + ks * 16, 264);
                wmma::load_matrix_sync(bl, Ml + (wn * 16) * 264 + b * 64 + ks * 16, 264);
                #pragma unroll
                for (int t = 0; t < 2; t++) {
                    wmma::mma_sync(acc2[t], ah[t], bh, acc2[t]);
                    wmma::mma_sync(acc2[t], ah[t], bl, acc2[t]);
                    wmma::mma_sync(acc2[t], al[t], bh, acc2[t]);
                }
            }
            __syncthreads();
        }
        #pragma unroll
        for (int t = 0; t < 2; t++)
            wmma::store_matrix_sync(stg + (rm + 16 * t) * 68 + wn * 16, acc2[t], 68,
                                    wmma::mem_row_major);
        __syncthreads();
    }

    // ====== softmax (threads 0..63) + attn tiles ======
    {
        __nv_bfloat16* Ah = (__nv_bfloat16*)(smem + ATH_O);
        __nv_bfloat16* Al = (__nv_bfloat16*)(smem + ATL_O);
        if (tid < 64) {
            float* lr = (float*)(smem + STG_O) + tid * 68;
            float m = -1e30f;
            #pragma unroll
            for (int c = 0; c < 64; c++) m = fmaxf(m, lr[c]);
            float sum = 0.f;
            #pragma unroll
            for (int c = 0; c < 64; c++) {
                float e = __expf((lr[c] - m) * 0.0625f);
                lr[c] = e; sum += e;
            }
            float inv = 1.0f / sum;
            float* arow = att + (row0 + tid) * 64;
            #pragma unroll
            for (int c = 0; c < 64; c += 4) {
                float4 v = *(float4*)(lr + c);
                v.x *= inv; v.y *= inv; v.z *= inv; v.w *= inv;
                *(float4*)(arow + c) = v;
                uint16_t h, l;
                split1(v.x, h, l); Ah[tid*72+c]   = __ushort_as_bfloat16(h); Al[tid*72+c]   = __ushort_as_bfloat16(l);
                split1(v.y, h, l); Ah[tid*72+c+1] = __ushort_as_bfloat16(h); Al[tid*72+c+1] = __ushort_as_bfloat16(l);
                split1(v.z, h, l); Ah[tid*72+c+2] = __ushort_as_bfloat16(h); Al[tid*72+c+2] = __ushort_as_bfloat16(l);
                split1(v.w, h, l); Ah[tid*72+c+3] = __ushort_as_bfloat16(h); Al[tid*72+c+3] = __ushort_as_bfloat16(l);
            }
        }
        __syncthreads();
    }

    // ---- prefetch GEMM4 chunk q=0 into buf0 ----
    #pragma unroll
    for (int i = 0; i < 2; i++) {
        int o = tid + i * NTH, r = o >> 2, sg = o & 3;
        cpa(sb + B4H(0) + r * 80 + sg * 16, g_dwh + r * 256 + sg * 8);
        cpa(sb + B4L(0) + r * 80 + sg * 16, g_dwl + r * 256 + sg * 8);
    }
    cpcommit();

    // ================== GEMM3: M = attn @ mem ==================
    FragC acc3[2][4];
    #pragma unroll
    for (int t = 0; t < 2; t++)
        #pragma unroll
        for (int f = 0; f < 4; f++) wmma::fill_fragment(acc3[t][f], 0.0f);
    {
        const __nv_bfloat16* Ah = (const __nv_bfloat16*)(smem + ATH_O);
        const __nv_bfloat16* Al = (const __nv_bfloat16*)(smem + ATL_O);
        const __nv_bfloat16* Mh = (const __nv_bfloat16*)(smem + MEMH_O);
        const __nv_bfloat16* Ml = (const __nv_bfloat16*)(smem + MEML_O);
        #pragma unroll
        for (int ks = 0; ks < 4; ks++) {
            FragA ah[2], al[2];
            #pragma unroll
            for (int t = 0; t < 2; t++) {
                wmma::load_matrix_sync(ah[t], Ah + (rm + 16 * t) * 72 + ks * 16, 72);
                wmma::load_matrix_sync(al[t], Al + (rm + 16 * t) * 72 + ks * 16, 72);
            }
            #pragma unroll
            for (int f = 0; f < 4; f++) {
                FragBr bh, bl;
                wmma::load_matrix_sync(bh, Mh + (ks * 16) * 264 + wn * 64 + f * 16, 264);
                wmma::load_matrix_sync(bl, Ml + (ks * 16) * 264 + wn * 64 + f * 16, 264);
                #pragma unroll
                for (int t = 0; t < 2; t++) {
                    wmma::mma_sync(acc3[t][f], ah[t], bh, acc3[t][f]);
                    wmma::mma_sync(acc3[t][f], ah[t], bl, acc3[t][f]);
                    wmma::mma_sync(acc3[t][f], al[t], bh, acc3[t][f]);
                }
            }
        }
    }
    __syncthreads();

    // ---- M epilogue: memout + M tiles ----
    {
        float* stg = (float*)(smem + MSTG_O);
        __nv_bfloat16* Mh = (__nv_bfloat16*)(smem + MH_O);
        __nv_bfloat16* Ml = (__nv_bfloat16*)(smem + ML_O);
        for (int q = 0; q < 4; q++) {
            if (wn == q)
                #pragma unroll
                for (int t = 0; t < 2; t++)
                    #pragma unroll
                    for (int f = 0; f < 4; f++)
                        wmma::store_matrix_sync(stg + (rm + 16 * t) * 68 + f * 16,
                                                acc3[t][f], 68, wmma::mem_row_major);
            __syncthreads();
            #pragma unroll
            for (int i = 0; i < 16; i++) {
                int idx = tid + i * NTH, r = idx >> 6, c = idx & 63;
                int gn = q * 64 + c;
                float v = stg[r * 68 + c];
                memout[(row0 + r) * 256 + gn] = v;
                uint16_t h, l; split1(v, h, l);
                Mh[r * 264 + gn] = __ushort_as_bfloat16(h);
                Ml[r * 264 + gn] = __ushort_as_bfloat16(l);
            }
            __syncthreads();
        }
    }

    // ================== GEMM4: recon = M @ dec_w^T + dec_b ==================
    {
        const __nv_bfloat16* Mh = (const __nv_bfloat16*)(smem + MH_O);
        const __nv_bfloat16* Ml = (const __nv_bfloat16*)(smem + ML_O);
        FragC acc4[2][2];
        for (int q = 0; q < 32; q++) {
            const int nt = q >> 3, kc = q & 7, buf = q & 1;
            if (kc == 0) {
                #pragma unroll
                for (int t = 0; t < 2; t++)
                    #pragma unroll
                    for (int f = 0; f < 2; f++) wmma::fill_fragment(acc4[t][f], 0.0f);
            }
            if (q < 31) {
                const int qp = q + 1, ntn = qp >> 3, kcn = qp & 7, nb = buf ^ 1;
                #pragma unroll
                for (int i = 0; i < 2; i++) {
                    int o = tid + i * NTH, r = o >> 2, sg = o & 3;
                    cpa(sb + B4H(nb) + r * 80 + sg * 16,
                        g_dwh + (ntn * 128 + r) * 256 + kcn * 32 + sg * 8);
                    cpa(sb + B4L(nb) + r * 80 + sg * 16,
                        g_dwl + (ntn * 128 + r) * 256 + kcn * 32 + sg * 8);
                }
                cpcommit(); cpwait<1>();
            } else cpwait<0>();
            __syncthreads();
            const __nv_bfloat16* Bh = (const __nv_bfloat16*)(smem + B4H(buf));
            const __nv_bfloat16* Bl = (const __nv_bfloat16*)(smem + B4L(buf));
            #pragma unroll
            for (int ks = 0; ks < 2; ks++) {
                FragA ah[2], al[2];
                #pragma unroll
                for (int t = 0; t < 2; t++) {
                    wmma::load_matrix_sync(ah[t], Mh + (rm + 16 * t) * 264 + kc * 32 + ks * 16, 264);
                    wmma::load_matrix_sync(al[t], Ml + (rm + 16 * t) * 264 + kc * 32 + ks * 16, 264);
                }
                #pragma unroll
                for (int f = 0; f < 2; f++) {
                    FragBc bh, bl;
                    wmma::load_matrix_sync(bh, Bh + (wn * 32 + f * 16) * 40 + ks * 16, 40);
                    wmma::load_matrix_sync(bl, Bl + (wn * 32 + f * 16) * 40 + ks * 16, 40);
                    #pragma unroll
                    for (int t = 0; t < 2; t++) {
                        wmma::mma_sync(acc4[t][f], ah[t], bh, acc4[t][f]);
                        wmma::mma_sync(acc4[t][f], ah[t], bl, acc4[t][f]);
                        wmma::mma_sync(acc4[t][f], al[t], bh, acc4[t][f]);
                    }
                }
            }
            __syncthreads();
            if (kc == 7) {
                float* stg = (float*)(smem + MSTG_O);
                for (int f = 0; f < 2; f++) {
                    #pragma unroll
                    for (int t = 0; t < 2; t++)
                        wmma::store_matrix_sync(stg + (rm + 16 * t) * 68 + wn * 16,
                                                acc4[t][f], 68, wmma::mem_row_major);
                    __syncthreads();
                    #pragma unroll
                    for (int i = 0; i < 16; i++) {
                        int idx = tid + i * NTH, r = idx >> 6, c = idx & 63;
                        int gn = (c >> 4) * 32 + f * 16 + (c & 15);
                        int d = nt * 128 + gn;
                        recon[(row0 + r) * 512 + d] = stg[r * 68 + c] + __ldg(dec_b_ + d);
                    }
                    __syncthreads();
                }
            }
        }
    }
}

extern "C" void kernel_launch(void* const* d_in, const int* in_sizes, int n_in,
                              void* d_out, int out_size)
{
    const float* seq   = (const float*)d_in[0];
    const float* enc_w = (const float*)d_in[1];
    const float* enc_b = (const float*)d_in[2];
    const float* memw  = (const float*)d_in[3];
    const float* dec_w = (const float*)d_in[4];
    const float* dec_b = (const float*)d_in[5];

    const long R = (long)in_sizes[0] / 512;   // 65536

    float* out    = (float*)d_out;
    float* recon  = out;
    float* att    = out + R * 512;
    float* memout = att + R * 64;

    split_small<<<272, 256>>>((const float4*)enc_w, (const float4*)dec_w, (const float4*)memw);

    cudaFuncSetAttribute(mwm4, cudaFuncAttributeMaxDynamicSharedMemorySize, SMEM_TOTAL);
    mwm4<<<(unsigned)(R / 64), NTH, SMEM_TOTAL>>>(seq, enc_b, dec_b, recon, att, memout);
}